// round 16
// baseline (speedup 1.0000x reference)
#include <cuda_runtime.h>
#include <cuda_fp16.h>
#include <cstdint>

#define NB 2048
#define NV 5023
#define NC 15069          // NV*3
#define CPAD 15168        // 79 * 192
#define KU4 12            // uint4 per packed row (96 fp16 = 192B)
#define NVC 64            // v-chunks for jpre
#define VCS 79            // ceil(5023/64)

// ---------------- device scratch (no allocation allowed) ----------------
__device__ uint4 g_Wh4[CPAD * KU4];   // W fp16, [c][96] rows (k contiguous)
__device__ uint4 g_Xh4[NB * KU4];     // X fp16, [b][96] rows
__device__ float g_A[NB * 60];        // [b][j][3x4] relative transforms
__device__ float g_JSp[NVC * 765];    // partial joint-regressor contractions
__device__ float g_JS[765];           // reduced

__device__ __forceinline__ uint32_t smem_u32(const void* p) {
    uint32_t a;
    asm("{ .reg .u64 t; cvta.to.shared.u64 t, %1; cvt.u32.u64 %0, t; }"
        : "=r"(a) : "l"(p));
    return a;
}

// ---- packed f32x2 helpers (Blackwell FFMA2) ----
__device__ __forceinline__ uint64_t pack2(float lo, float hi) {
    uint64_t r;
    asm("mov.b64 %0, {%1, %2};" : "=l"(r) : "f"(lo), "f"(hi));
    return r;
}
__device__ __forceinline__ void unpack2(uint64_t v, float& lo, float& hi) {
    asm("mov.b64 {%0, %1}, %2;" : "=f"(lo), "=f"(hi) : "l"(v));
}
__device__ __forceinline__ void fma2(uint64_t& d, uint64_t a, uint64_t b) {
    asm("fma.rn.f32x2 %0, %1, %2, %3;" : "=l"(d) : "l"(a), "l"(b), "l"(d));
}

#define LDMATRIX_X4(r0, r1, r2, r3, addr) \
    asm volatile("ldmatrix.sync.aligned.m8n8.x4.shared.b16 {%0,%1,%2,%3}, [%4];" \
        : "=r"(r0), "=r"(r1), "=r"(r2), "=r"(r3) : "r"(addr))

#define MMA_FP16(c, a0, a1, a2, a3, b0, b1) \
    asm volatile("mma.sync.aligned.m16n8k16.row.col.f32.f16.f16.f32 " \
        "{%0,%1,%2,%3}, {%4,%5,%6,%7}, {%8,%9}, {%0,%1,%2,%3};" \
        : "+f"((c)[0]), "+f"((c)[1]), "+f"((c)[2]), "+f"((c)[3]) \
        : "r"(a0), "r"(a1), "r"(a2), "r"(a3), "r"(b0), "r"(b1))

// ---------- fused prologue: blocks [0,60) pack W, blocks [60,300) jpre ----------
__global__ void pre_kernel(const float* __restrict__ vt,
                           const float* __restrict__ SD,
                           const float* __restrict__ PD,
                           const float* __restrict__ Jreg) {
    extern __shared__ __half sW[];
    const int tid = threadIdx.x;
    if (blockIdx.x < 60) {
        // ---------------- packW ----------------
        const int c0 = blockIdx.x * 256;
        {
            float v[36];
            const int c = tid, cg = c0 + c;
            #pragma unroll
            for (int k = 0; k < 36; k++)
                v[k] = (cg < NC) ? __ldg(PD + k * NC + cg) : 0.f;
            #pragma unroll
            for (int k = 0; k < 36; k++)
                sW[c * 104 + 50 + k] = __float2half_rn(v[k]);
        }
        {
            int wid = tid >> 5, lane = tid & 31;
            #pragma unroll 8
            for (int ci = 0; ci < 32; ci++) {
                int c = wid + ci * 8;
                int cg = c0 + c;
                float v0 = (cg < NC && lane < 50) ? __ldg(SD + cg * 150 + 100 + lane) : 0.f;
                float v1 = (cg < NC && lane < 18) ? __ldg(SD + cg * 150 + 132 + lane) : 0.f;
                if (lane < 50) sW[c * 104 + lane] = __float2half_rn(v0);
                if (lane < 18) sW[c * 104 + 32 + lane] = __float2half_rn(v1);
            }
        }
        {
            const int c = tid, cg = c0 + c;
            float v = (cg < NC) ? __ldg(vt + cg) : 0.f;
            sW[c * 104 + 86] = __float2half_rn(v);
            #pragma unroll
            for (int k = 87; k < 96; k++) sW[c * 104 + k] = __float2half_rn(0.f);
        }
        __syncthreads();
        #pragma unroll
        for (int it = 0; it < 12; it++) {
            int i = tid + it * 256;
            int c = i / 12, u = i - c * 12;
            int cg = c0 + c;
            if (cg < CPAD)
                g_Wh4[cg * 12 + u] = *reinterpret_cast<uint4*>(&sW[c * 104 + u * 8]);
        }
    } else {
        // ---------------- jpre ----------------
        int gw = (blockIdx.x - 60) * 8 + (tid >> 5);
        int lane = tid & 31;
        if (gw >= NVC * 30) return;
        int vc = gw / 30, rem = gw % 30;
        int e = rem >> 1, lh = rem & 1;
        int l = lh * 26 + lane;
        bool active = lane < (lh ? 25 : 26);
        int j = e / 3, k = e % 3;
        int v0 = vc * VCS, v1 = min(v0 + VCS, NV);
        float acc = 0.f;
        if (active) {
            #pragma unroll 8
            for (int v = v0; v < v1; v++) {
                float w = __ldg(Jreg + j * NV + v);
                float s = (l < 50) ? __ldg(SD + (v * 3 + k) * 150 + 100 + l)
                                   : __ldg(vt + v * 3 + k);
                acc = fmaf(w, s, acc);
            }
            g_JSp[vc * 765 + e * 51 + l] = acc;
        }
    }
}

__global__ void jred_kernel() {
    int i = blockIdx.x * blockDim.x + threadIdx.x;
    if (i >= 765) return;
    float s = 0.f;
    #pragma unroll
    for (int vc = 0; vc < NVC; vc++) s += g_JSp[vc * 765 + i];
    g_JS[i] = s;
}

// ------------------------------------- per-batch: rodrigues, FK, A, X rows
static constexpr int BSM_TOTAL = 41984;

__global__ __launch_bounds__(64)
void batch_kernel(const float* __restrict__ expr,
                  const float* __restrict__ pose,
                  float* __restrict__ out_pf,
                  float* __restrict__ out_A) {
    extern __shared__ char bsm[];
    float* ex  = reinterpret_cast<float*>(bsm);
    float* po  = reinterpret_cast<float*>(bsm + 12800);
    float* sJS = reinterpret_cast<float*>(bsm + 16640);
    uint32_t* sXu = reinterpret_cast<uint32_t*>(bsm);          // [64][48]
    float* sA  = reinterpret_cast<float*>(bsm + 12288);        // [64][80]
    float* spf = reinterpret_cast<float*>(bsm + 32768);        // [64][36]

    const int tid = threadIdx.x;
    const int bBase = blockIdx.x * 64;
    #pragma unroll
    for (int it = 0; it < 12; it++) {
        int i = tid + it * 64;
        if (i < 765) sJS[i] = __ldg(g_JS + i);
    }
    #pragma unroll
    for (int it = 0; it < 50; it++)
        ex[tid + it * 64] = __ldg(expr + bBase * 50 + tid + it * 64);
    #pragma unroll
    for (int it = 0; it < 15; it++)
        po[tid + it * 64] = __ldg(pose + bBase * 15 + tid + it * 64);
    __syncthreads();

    __half xh[96];
    #pragma unroll
    for (int kk = 0; kk < 96; kk++) xh[kk] = __float2half_rn(0.f);

    float jnt[15];
    #pragma unroll
    for (int e = 0; e < 15; e++) jnt[e] = sJS[e * 51 + 50];
    #pragma unroll 5
    for (int l = 0; l < 50; l++) {
        float ev = ex[tid * 50 + l];
        xh[l] = __float2half_rn(ev);
        #pragma unroll
        for (int e = 0; e < 15; e++) jnt[e] = fmaf(ev, sJS[e * 51 + l], jnt[e]);
    }
    xh[86] = __float2half_rn(1.f);

    float R[5][9];
    #pragma unroll
    for (int j = 0; j < 5; j++) {
        float x = po[tid * 15 + j * 3 + 0];
        float y = po[tid * 15 + j * 3 + 1];
        float z = po[tid * 15 + j * 3 + 2];
        float ax = x + 1e-8f, ay = y + 1e-8f, az = z + 1e-8f;
        float ang = sqrtf(ax * ax + ay * ay + az * az);
        float inv = 1.f / ang;
        float rx = x * inv, ry = y * inv, rz = z * inv;
        float s = sinf(ang), cth = cosf(ang), t = 1.f - cth;
        float s2 = rx * rx + ry * ry + rz * rz;
        R[j][0] = 1.f + t * (rx * rx - s2);
        R[j][1] = -s * rz + t * rx * ry;
        R[j][2] =  s * ry + t * rx * rz;
        R[j][3] =  s * rz + t * rx * ry;
        R[j][4] = 1.f + t * (ry * ry - s2);
        R[j][5] = -s * rx + t * ry * rz;
        R[j][6] = -s * ry + t * rx * rz;
        R[j][7] =  s * rx + t * ry * rz;
        R[j][8] = 1.f + t * (rz * rz - s2);
    }

    #pragma unroll
    for (int j = 1; j < 5; j++)
        #pragma unroll
        for (int idx = 0; idx < 9; idx++) {
            int m = (j - 1) * 9 + idx;
            float v = R[j][idx] - ((idx == 0 || idx == 4 || idx == 8) ? 1.f : 0.f);
            xh[50 + m] = __float2half_rn(v);
            spf[tid * 36 + m] = v;
        }

    __syncthreads();   // ex/po/sJS reads done; safe to overlay

    {
        const uint32_t* xp = reinterpret_cast<const uint32_t*>(xh);
        #pragma unroll
        for (int u = 0; u < 48; u++) sXu[tid * 48 + u] = xp[u];
    }

    float G[5][12];
    #pragma unroll
    for (int p = 0; p < 3; p++) {
        G[0][p * 4 + 0] = R[0][p * 3 + 0];
        G[0][p * 4 + 1] = R[0][p * 3 + 1];
        G[0][p * 4 + 2] = R[0][p * 3 + 2];
        G[0][p * 4 + 3] = jnt[p];
    }
    #pragma unroll
    for (int j = 1; j < 5; j++) {
        const int par = (j == 1) ? 0 : 1;
        float t0 = jnt[j * 3 + 0] - jnt[par * 3 + 0];
        float t1 = jnt[j * 3 + 1] - jnt[par * 3 + 1];
        float t2 = jnt[j * 3 + 2] - jnt[par * 3 + 2];
        #pragma unroll
        for (int p = 0; p < 3; p++) {
            float g0 = G[par][p * 4 + 0], g1 = G[par][p * 4 + 1];
            float g2 = G[par][p * 4 + 2], g3 = G[par][p * 4 + 3];
            #pragma unroll
            for (int q = 0; q < 3; q++)
                G[j][p * 4 + q] = g0 * R[j][q] + g1 * R[j][3 + q] + g2 * R[j][6 + q];
            G[j][p * 4 + 3] = g0 * t0 + g1 * t1 + g2 * t2 + g3;
        }
    }
    #pragma unroll
    for (int j = 0; j < 5; j++) {
        #pragma unroll
        for (int p = 0; p < 3; p++) {
            float r0 = G[j][p * 4 + 0], r1 = G[j][p * 4 + 1], r2 = G[j][p * 4 + 2];
            float ta = G[j][p * 4 + 3] -
                       (r0 * jnt[j * 3 + 0] + r1 * jnt[j * 3 + 1] + r2 * jnt[j * 3 + 2]);
            int sb = tid * 80 + j * 16 + p * 4;
            sA[sb + 0] = r0; sA[sb + 1] = r1; sA[sb + 2] = r2; sA[sb + 3] = ta;
        }
        int sb = tid * 80 + j * 16 + 12;
        sA[sb + 0] = 0.f; sA[sb + 1] = 0.f; sA[sb + 2] = 0.f; sA[sb + 3] = 1.f;
    }
    __syncthreads();

    {
        uint4* dst = g_Xh4 + bBase * 12;
        const uint4* src = reinterpret_cast<const uint4*>(sXu);
        #pragma unroll
        for (int it = 0; it < 12; it++) dst[tid + it * 64] = src[tid + it * 64];
    }
    {
        float4* dst = reinterpret_cast<float4*>(out_A + (size_t)bBase * 80);
        const float4* src = reinterpret_cast<const float4*>(sA);
        #pragma unroll
        for (int it = 0; it < 20; it++) dst[tid + it * 64] = src[tid + it * 64];
    }
    {
        float4* dst = reinterpret_cast<float4*>(g_A + (size_t)bBase * 60);
        const float4* src = reinterpret_cast<const float4*>(sA);
        #pragma unroll
        for (int it = 0; it < 15; it++) {
            int i = tid + it * 64;
            int b = i / 15, u = i - b * 15;
            int j = u / 3, r = u - j * 3;
            dst[i] = src[b * 20 + j * 4 + r];
        }
    }
    {
        float4* dst = reinterpret_cast<float4*>(out_pf + (size_t)bBase * 36);
        const float4* src = reinterpret_cast<const float4*>(spf);
        #pragma unroll
        for (int it = 0; it < 9; it++) dst[tid + it * 64] = src[tid + it * 64];
    }
}

// ==== HMMA GEMM (64b x 192c x 96k fp16) + fused LBS, 3 CTAs/SM ====
static constexpr int LDB = 208;                   // bytes per smem row
static constexpr int SM_XH = 0;                   // X: 64*208  = 13312
static constexpr int SM_WH = 13312;               // W: 192*208 = 39936 -> 53248
static constexpr int SM_AS = 53248;               // A: 64*60*4 = 15360 -> 68608
static constexpr int SM_WJ = 68608;               // wjs: 320*4 = 1280  -> 69888
static constexpr int SM_TOTAL = 69888;            // 3 CTAs = 209664 <= 228KB
// D overlays the GEMM tiles after they are dead:
static constexpr int LDD = 196;                   // D stride in floats
static constexpr int SM_DS = 0;                   // float[64][196] = 50176 (< 53248)

__global__ __launch_bounds__(256, 3)
void skin_kernel(const float* __restrict__ lbs, float* __restrict__ out) {
    extern __shared__ char sm[];
    const uint32_t smb = smem_u32(sm);
    const int tid = threadIdx.x;
    const int wid = tid >> 5, lane = tid & 31;   // 8 warps
    const int bBase = blockIdx.y * 64;
    const int cTile = blockIdx.x;                // 192 comps = 64 vertices
    const int vBase = cTile * 64;

    // ---- stage everything up front: wjs (320 floats), X, W, A ----
    float* wjs = reinterpret_cast<float*>(sm + SM_WJ);
    #pragma unroll
    for (int it = 0; it < 2; it++) {
        int i = tid + it * 256;
        if (i < 320)
            wjs[i] = (vBase + i / 5 < NV) ? lbs[vBase * 5 + i] : 0.f;
    }
    #pragma unroll
    for (int it = 0; it < 3; it++) {
        int i = tid + it * 256;
        int r = i / KU4, u = i - r * KU4;
        *reinterpret_cast<uint4*>(sm + SM_XH + r * LDB + u * 16) =
            g_Xh4[(bBase + r) * KU4 + u];
    }
    #pragma unroll
    for (int it = 0; it < 9; it++) {
        int i = tid + it * 256;
        int r = i / KU4, u = i - r * KU4;
        *reinterpret_cast<uint4*>(sm + SM_WH + r * LDB + u * 16) =
            g_Wh4[(cTile * 192 + r) * KU4 + u];
    }
    {
        float4* As4 = reinterpret_cast<float4*>(sm + SM_AS);
        const float4* gA4 = reinterpret_cast<const float4*>(g_A);
        #pragma unroll
        for (int it = 0; it < 4; it++) {
            int i = tid + it * 256;
            if (i < 64 * 15)
                As4[i] = gA4[(size_t)bBase * 15 + i];
        }
    }
    __syncthreads();

    // ---- warp tile: 32 rows x 48 cols; warps 2x4 ----
    const int wm = wid & 1, wn = wid >> 1;
    float acc[2][6][4];
    #pragma unroll
    for (int mi = 0; mi < 2; mi++)
        #pragma unroll
        for (int ni = 0; ni < 6; ni++)
            #pragma unroll
            for (int e = 0; e < 4; e++) acc[mi][ni][e] = 0.f;

    const int a_row = wm * 32 + (lane & 7) + (lane & 8);
    const uint32_t a_off = a_row * LDB + ((lane >> 4) * 8) * 2;
    const int b_row = wn * 48 + ((lane >> 4) << 3) + (lane & 7);
    const uint32_t b_off = b_row * LDB + (((lane >> 3) & 1) * 8) * 2;
    const uint32_t xh = smb + SM_XH + a_off;
    const uint32_t wb = smb + SM_WH + b_off;

    #pragma unroll
    for (int k = 0; k < 6; k++) {
        uint32_t bfr[3][4];
        #pragma unroll
        for (int n2 = 0; n2 < 3; n2++)
            LDMATRIX_X4(bfr[n2][0], bfr[n2][1], bfr[n2][2], bfr[n2][3],
                        wb + n2 * 16 * LDB + k * 32);
        uint32_t a[2][4];
        LDMATRIX_X4(a[0][0], a[0][1], a[0][2], a[0][3], xh + k * 32);
        LDMATRIX_X4(a[1][0], a[1][1], a[1][2], a[1][3], xh + 16 * LDB + k * 32);
        #pragma unroll
        for (int mi = 0; mi < 2; mi++)
            #pragma unroll
            for (int ni = 0; ni < 6; ni++)
                MMA_FP16(acc[mi][ni], a[mi][0], a[mi][1], a[mi][2], a[mi][3],
                         bfr[ni >> 1][(ni & 1) * 2], bfr[ni >> 1][(ni & 1) * 2 + 1]);
    }
    __syncthreads();   // tiles dead; D may overlay

    // ---- stage D (64 x 196 f32) ----
    float* Ds = reinterpret_cast<float*>(sm + SM_DS);
    #pragma unroll
    for (int mi = 0; mi < 2; mi++)
        #pragma unroll
        for (int ni = 0; ni < 6; ni++) {
            int row = wm * 32 + mi * 16 + (lane >> 2);
            int col = wn * 48 + ni * 8 + (lane & 3) * 2;
            *reinterpret_cast<float2*>(Ds + row * LDD + col) =
                make_float2(acc[mi][ni][0], acc[mi][ni][1]);
            *reinterpret_cast<float2*>(Ds + (row + 8) * LDD + col) =
                make_float2(acc[mi][ni][2], acc[mi][ni][3]);
        }
    __syncthreads();

    // ---- fused LBS epilogue: results written IN PLACE into Ds ----
    const float* As = reinterpret_cast<const float*>(sm + SM_AS);
    const int lv = lane * 2;
    uint64_t w0[5], w1[5];
    #pragma unroll
    for (int j = 0; j < 5; j++) {
        float a = wjs[lv * 5 + j];
        float b = wjs[lv * 5 + 5 + j];
        w0[j] = pack2(a, a);
        w1[j] = pack2(b, b);
    }

    #pragma unroll 2
    for (int i = 0; i < 8; i++) {
        const int bl = wid + 8 * i;              // 0..63
        const ulonglong2* Ab = reinterpret_cast<const ulonglong2*>(As + bl * 60);
        uint64_t M0[6], M1[6];
        #pragma unroll
        for (int e = 0; e < 6; e++) { M0[e] = 0ull; M1[e] = 0ull; }
        #pragma unroll
        for (int j = 0; j < 5; j++) {
            ulonglong2 a0 = Ab[j * 3 + 0];
            ulonglong2 a1 = Ab[j * 3 + 1];
            ulonglong2 a2 = Ab[j * 3 + 2];
            fma2(M0[0], w0[j], a0.x); fma2(M0[1], w0[j], a0.y);
            fma2(M0[2], w0[j], a1.x); fma2(M0[3], w0[j], a1.y);
            fma2(M0[4], w0[j], a2.x); fma2(M0[5], w0[j], a2.y);
            fma2(M1[0], w1[j], a0.x); fma2(M1[1], w1[j], a0.y);
            fma2(M1[2], w1[j], a1.x); fma2(M1[3], w1[j], a1.y);
            fma2(M1[4], w1[j], a2.x); fma2(M1[5], w1[j], a2.y);
        }
        float* Dr = Ds + bl * LDD + lv * 3;      // thread-private 6 floats
        float2 d0 = *reinterpret_cast<const float2*>(Dr);
        float2 d1 = *reinterpret_cast<const float2*>(Dr + 2);
        float2 d2 = *reinterpret_cast<const float2*>(Dr + 4);

        float m00, m01, m02, m03, m10, m11, m12, m13, m20, m21, m22, m23;
        unpack2(M0[0], m00, m01); unpack2(M0[1], m02, m03);
        unpack2(M0[2], m10, m11); unpack2(M0[3], m12, m13);
        unpack2(M0[4], m20, m21); unpack2(M0[5], m22, m23);
        float o0 = fmaf(m00, d0.x, fmaf(m01, d0.y, fmaf(m02, d1.x, m03)));
        float o1 = fmaf(m10, d0.x, fmaf(m11, d0.y, fmaf(m12, d1.x, m13)));
        float o2 = fmaf(m20, d0.x, fmaf(m21, d0.y, fmaf(m22, d1.x, m23)));

        unpack2(M1[0], m00, m01); unpack2(M1[1], m02, m03);
        unpack2(M1[2], m10, m11); unpack2(M1[3], m12, m13);
        unpack2(M1[4], m20, m21); unpack2(M1[5], m22, m23);
        float o3 = fmaf(m00, d1.y, fmaf(m01, d2.x, fmaf(m02, d2.y, m03)));
        float o4 = fmaf(m10, d1.y, fmaf(m11, d2.x, fmaf(m12, d2.y, m13)));
        float o5 = fmaf(m20, d1.y, fmaf(m21, d2.x, fmaf(m22, d2.y, m23)));

        // in-place overwrite (reads above complete before these stores)
        *reinterpret_cast<float2*>(Dr)     = make_float2(o0, o1);
        *reinterpret_cast<float2*>(Dr + 2) = make_float2(o2, o3);
        *reinterpret_cast<float2*>(Dr + 4) = make_float2(o4, o5);
    }
    __syncthreads();

    // ---- coalesced copy Ds -> out: col = tid (192 active), strided rows ----
    if (tid < 192) {
        const float* src = Ds + tid;
        float* dst = out + (size_t)bBase * NC + (size_t)vBase * 3 + tid;
        if (vBase + 64 <= NV) {                  // full tile (78 of 79)
            #pragma unroll 8
            for (int bl = 0; bl < 64; bl++)
                dst[(size_t)bl * NC] = src[bl * LDD];
        } else if (tid < (NV - vBase) * 3) {     // tail tile, clamp columns
            #pragma unroll 8
            for (int bl = 0; bl < 64; bl++)
                dst[(size_t)bl * NC] = src[bl * LDD];
        }
    }
}

// ---------------------------------------------------------------- launch
extern "C" void kernel_launch(void* const* d_in, const int* in_sizes, int n_in,
                              void* d_out, int out_size) {
    const float* expr = (const float*)d_in[0];  // [2048,50]
    const float* pose = (const float*)d_in[1];  // [2048,15]
    const float* vt   = (const float*)d_in[2];  // [5023,3]
    const float* SD   = (const float*)d_in[3];  // [5023,3,150]
    const float* PD   = (const float*)d_in[4];  // [36,15069]
    const float* Jreg = (const float*)d_in[5];  // [5,5023]
    const float* lbs  = (const float*)d_in[6];  // [5023,5]

    float* out       = (float*)d_out;
    float* out_verts = out;                       // [B,V,3]
    float* out_pf    = out + (size_t)NB * NV * 3; // [B,36]
    float* out_A     = out_pf + (size_t)NB * 36;  // [B,5,4,4]

    const int PRE_SMEM = 256 * 104 * 2;           // 53248
    cudaFuncSetAttribute(pre_kernel,
                         cudaFuncAttributeMaxDynamicSharedMemorySize, PRE_SMEM);
    cudaFuncSetAttribute(batch_kernel,
                         cudaFuncAttributeMaxDynamicSharedMemorySize, BSM_TOTAL);
    cudaFuncSetAttribute(skin_kernel,
                         cudaFuncAttributeMaxDynamicSharedMemorySize, SM_TOTAL);

    pre_kernel<<<300, 256, PRE_SMEM>>>(vt, SD, PD, Jreg);
    jred_kernel<<<3, 256>>>();
    batch_kernel<<<NB / 64, 64, BSM_TOTAL>>>(expr, pose, out_pf, out_A);
    dim3 grid(79, 32);
    skin_kernel<<<grid, 256, SM_TOTAL>>>(lbs, out_verts);
}

// round 17
// speedup vs baseline: 1.6738x; 1.6738x over previous
#include <cuda_runtime.h>
#include <cuda_fp16.h>
#include <cstdint>

#define NB 2048
#define NV 5023
#define NC 15069          // NV*3
#define CPAD 15168        // 79 * 192
#define KU4 12            // uint4 per packed row (96 fp16 = 192B)
#define NVC 64            // v-chunks for jpre
#define VCS 79            // ceil(5023/64)

// ---------------- device scratch (no allocation allowed) ----------------
__device__ uint4 g_Wh4[CPAD * KU4];   // W fp16, [c][96] rows (k contiguous)
__device__ uint4 g_Xh4[NB * KU4];     // X fp16, [b][96] rows
__device__ float g_A[NB * 60];        // [b][j][3x4] relative transforms
__device__ float g_JSp[NVC * 765];    // partial joint-regressor contractions
__device__ float g_JS[765];           // reduced

__device__ __forceinline__ uint32_t smem_u32(const void* p) {
    uint32_t a;
    asm("{ .reg .u64 t; cvta.to.shared.u64 t, %1; cvt.u32.u64 %0, t; }"
        : "=r"(a) : "l"(p));
    return a;
}

// ---- packed f32x2 helpers (Blackwell FFMA2) ----
__device__ __forceinline__ uint64_t pack2(float lo, float hi) {
    uint64_t r;
    asm("mov.b64 %0, {%1, %2};" : "=l"(r) : "f"(lo), "f"(hi));
    return r;
}
__device__ __forceinline__ void unpack2(uint64_t v, float& lo, float& hi) {
    asm("mov.b64 {%0, %1}, %2;" : "=f"(lo), "=f"(hi) : "l"(v));
}
__device__ __forceinline__ void fma2(uint64_t& d, uint64_t a, uint64_t b) {
    asm("fma.rn.f32x2 %0, %1, %2, %3;" : "=l"(d) : "l"(a), "l"(b), "l"(d));
}

#define LDMATRIX_X4(r0, r1, r2, r3, addr) \
    asm volatile("ldmatrix.sync.aligned.m8n8.x4.shared.b16 {%0,%1,%2,%3}, [%4];" \
        : "=r"(r0), "=r"(r1), "=r"(r2), "=r"(r3) : "r"(addr))

#define MMA_FP16(c, a0, a1, a2, a3, b0, b1) \
    asm volatile("mma.sync.aligned.m16n8k16.row.col.f32.f16.f16.f32 " \
        "{%0,%1,%2,%3}, {%4,%5,%6,%7}, {%8,%9}, {%0,%1,%2,%3};" \
        : "+f"((c)[0]), "+f"((c)[1]), "+f"((c)[2]), "+f"((c)[3]) \
        : "r"(a0), "r"(a1), "r"(a2), "r"(a3), "r"(b0), "r"(b1))

// ---------- fused prologue: blocks [0,60) pack W, blocks [60,300) jpre ----------
__global__ void pre_kernel(const float* __restrict__ vt,
                           const float* __restrict__ SD,
                           const float* __restrict__ PD,
                           const float* __restrict__ Jreg) {
    extern __shared__ __half sW[];
    const int tid = threadIdx.x;
    if (blockIdx.x < 60) {
        // ---------------- packW ----------------
        const int c0 = blockIdx.x * 256;
        {
            float v[36];
            const int c = tid, cg = c0 + c;
            #pragma unroll
            for (int k = 0; k < 36; k++)
                v[k] = (cg < NC) ? __ldg(PD + k * NC + cg) : 0.f;
            #pragma unroll
            for (int k = 0; k < 36; k++)
                sW[c * 104 + 50 + k] = __float2half_rn(v[k]);
        }
        {
            int wid = tid >> 5, lane = tid & 31;
            #pragma unroll 8
            for (int ci = 0; ci < 32; ci++) {
                int c = wid + ci * 8;
                int cg = c0 + c;
                float v0 = (cg < NC && lane < 50) ? __ldg(SD + cg * 150 + 100 + lane) : 0.f;
                float v1 = (cg < NC && lane < 18) ? __ldg(SD + cg * 150 + 132 + lane) : 0.f;
                if (lane < 50) sW[c * 104 + lane] = __float2half_rn(v0);
                if (lane < 18) sW[c * 104 + 32 + lane] = __float2half_rn(v1);
            }
        }
        {
            const int c = tid, cg = c0 + c;
            float v = (cg < NC) ? __ldg(vt + cg) : 0.f;
            sW[c * 104 + 86] = __float2half_rn(v);
            #pragma unroll
            for (int k = 87; k < 96; k++) sW[c * 104 + k] = __float2half_rn(0.f);
        }
        __syncthreads();
        #pragma unroll
        for (int it = 0; it < 12; it++) {
            int i = tid + it * 256;
            int c = i / 12, u = i - c * 12;
            int cg = c0 + c;
            if (cg < CPAD)
                g_Wh4[cg * 12 + u] = *reinterpret_cast<uint4*>(&sW[c * 104 + u * 8]);
        }
    } else {
        // ---------------- jpre ----------------
        int gw = (blockIdx.x - 60) * 8 + (tid >> 5);
        int lane = tid & 31;
        if (gw >= NVC * 30) return;
        int vc = gw / 30, rem = gw % 30;
        int e = rem >> 1, lh = rem & 1;
        int l = lh * 26 + lane;
        bool active = lane < (lh ? 25 : 26);
        int j = e / 3, k = e % 3;
        int v0 = vc * VCS, v1 = min(v0 + VCS, NV);
        float acc = 0.f;
        if (active) {
            #pragma unroll 8
            for (int v = v0; v < v1; v++) {
                float w = __ldg(Jreg + j * NV + v);
                float s = (l < 50) ? __ldg(SD + (v * 3 + k) * 150 + 100 + l)
                                   : __ldg(vt + v * 3 + k);
                acc = fmaf(w, s, acc);
            }
            g_JSp[vc * 765 + e * 51 + l] = acc;
        }
    }
}

__global__ void jred_kernel() {
    int i = blockIdx.x * blockDim.x + threadIdx.x;
    if (i >= 765) return;
    float s = 0.f;
    #pragma unroll
    for (int vc = 0; vc < NVC; vc++) s += g_JSp[vc * 765 + i];
    g_JS[i] = s;
}

// ------------------------------------- per-batch: rodrigues, FK, A, X rows
static constexpr int BSM_TOTAL = 41984;

__global__ __launch_bounds__(64)
void batch_kernel(const float* __restrict__ expr,
                  const float* __restrict__ pose,
                  float* __restrict__ out_pf,
                  float* __restrict__ out_A) {
    extern __shared__ char bsm[];
    float* ex  = reinterpret_cast<float*>(bsm);
    float* po  = reinterpret_cast<float*>(bsm + 12800);
    float* sJS = reinterpret_cast<float*>(bsm + 16640);
    uint32_t* sXu = reinterpret_cast<uint32_t*>(bsm);          // [64][48]
    float* sA  = reinterpret_cast<float*>(bsm + 12288);        // [64][80]
    float* spf = reinterpret_cast<float*>(bsm + 32768);        // [64][36]

    const int tid = threadIdx.x;
    const int bBase = blockIdx.x * 64;
    #pragma unroll
    for (int it = 0; it < 12; it++) {
        int i = tid + it * 64;
        if (i < 765) sJS[i] = __ldg(g_JS + i);
    }
    #pragma unroll
    for (int it = 0; it < 50; it++)
        ex[tid + it * 64] = __ldg(expr + bBase * 50 + tid + it * 64);
    #pragma unroll
    for (int it = 0; it < 15; it++)
        po[tid + it * 64] = __ldg(pose + bBase * 15 + tid + it * 64);
    __syncthreads();

    __half xh[96];
    #pragma unroll
    for (int kk = 0; kk < 96; kk++) xh[kk] = __float2half_rn(0.f);

    float jnt[15];
    #pragma unroll
    for (int e = 0; e < 15; e++) jnt[e] = sJS[e * 51 + 50];
    #pragma unroll 5
    for (int l = 0; l < 50; l++) {
        float ev = ex[tid * 50 + l];
        xh[l] = __float2half_rn(ev);
        #pragma unroll
        for (int e = 0; e < 15; e++) jnt[e] = fmaf(ev, sJS[e * 51 + l], jnt[e]);
    }
    xh[86] = __float2half_rn(1.f);

    float R[5][9];
    #pragma unroll
    for (int j = 0; j < 5; j++) {
        float x = po[tid * 15 + j * 3 + 0];
        float y = po[tid * 15 + j * 3 + 1];
        float z = po[tid * 15 + j * 3 + 2];
        float ax = x + 1e-8f, ay = y + 1e-8f, az = z + 1e-8f;
        float ang = sqrtf(ax * ax + ay * ay + az * az);
        float inv = 1.f / ang;
        float rx = x * inv, ry = y * inv, rz = z * inv;
        float s = sinf(ang), cth = cosf(ang), t = 1.f - cth;
        float s2 = rx * rx + ry * ry + rz * rz;
        R[j][0] = 1.f + t * (rx * rx - s2);
        R[j][1] = -s * rz + t * rx * ry;
        R[j][2] =  s * ry + t * rx * rz;
        R[j][3] =  s * rz + t * rx * ry;
        R[j][4] = 1.f + t * (ry * ry - s2);
        R[j][5] = -s * rx + t * ry * rz;
        R[j][6] = -s * ry + t * rx * rz;
        R[j][7] =  s * rx + t * ry * rz;
        R[j][8] = 1.f + t * (rz * rz - s2);
    }

    #pragma unroll
    for (int j = 1; j < 5; j++)
        #pragma unroll
        for (int idx = 0; idx < 9; idx++) {
            int m = (j - 1) * 9 + idx;
            float v = R[j][idx] - ((idx == 0 || idx == 4 || idx == 8) ? 1.f : 0.f);
            xh[50 + m] = __float2half_rn(v);
            spf[tid * 36 + m] = v;
        }

    __syncthreads();   // ex/po/sJS reads done; safe to overlay

    {
        const uint32_t* xp = reinterpret_cast<const uint32_t*>(xh);
        #pragma unroll
        for (int u = 0; u < 48; u++) sXu[tid * 48 + u] = xp[u];
    }

    float G[5][12];
    #pragma unroll
    for (int p = 0; p < 3; p++) {
        G[0][p * 4 + 0] = R[0][p * 3 + 0];
        G[0][p * 4 + 1] = R[0][p * 3 + 1];
        G[0][p * 4 + 2] = R[0][p * 3 + 2];
        G[0][p * 4 + 3] = jnt[p];
    }
    #pragma unroll
    for (int j = 1; j < 5; j++) {
        const int par = (j == 1) ? 0 : 1;
        float t0 = jnt[j * 3 + 0] - jnt[par * 3 + 0];
        float t1 = jnt[j * 3 + 1] - jnt[par * 3 + 1];
        float t2 = jnt[j * 3 + 2] - jnt[par * 3 + 2];
        #pragma unroll
        for (int p = 0; p < 3; p++) {
            float g0 = G[par][p * 4 + 0], g1 = G[par][p * 4 + 1];
            float g2 = G[par][p * 4 + 2], g3 = G[par][p * 4 + 3];
            #pragma unroll
            for (int q = 0; q < 3; q++)
                G[j][p * 4 + q] = g0 * R[j][q] + g1 * R[j][3 + q] + g2 * R[j][6 + q];
            G[j][p * 4 + 3] = g0 * t0 + g1 * t1 + g2 * t2 + g3;
        }
    }
    #pragma unroll
    for (int j = 0; j < 5; j++) {
        #pragma unroll
        for (int p = 0; p < 3; p++) {
            float r0 = G[j][p * 4 + 0], r1 = G[j][p * 4 + 1], r2 = G[j][p * 4 + 2];
            float ta = G[j][p * 4 + 3] -
                       (r0 * jnt[j * 3 + 0] + r1 * jnt[j * 3 + 1] + r2 * jnt[j * 3 + 2]);
            int sb = tid * 80 + j * 16 + p * 4;
            sA[sb + 0] = r0; sA[sb + 1] = r1; sA[sb + 2] = r2; sA[sb + 3] = ta;
        }
        int sb = tid * 80 + j * 16 + 12;
        sA[sb + 0] = 0.f; sA[sb + 1] = 0.f; sA[sb + 2] = 0.f; sA[sb + 3] = 1.f;
    }
    __syncthreads();

    {
        uint4* dst = g_Xh4 + bBase * 12;
        const uint4* src = reinterpret_cast<const uint4*>(sXu);
        #pragma unroll
        for (int it = 0; it < 12; it++) dst[tid + it * 64] = src[tid + it * 64];
    }
    {
        float4* dst = reinterpret_cast<float4*>(out_A + (size_t)bBase * 80);
        const float4* src = reinterpret_cast<const float4*>(sA);
        #pragma unroll
        for (int it = 0; it < 20; it++) dst[tid + it * 64] = src[tid + it * 64];
    }
    {
        float4* dst = reinterpret_cast<float4*>(g_A + (size_t)bBase * 60);
        const float4* src = reinterpret_cast<const float4*>(sA);
        #pragma unroll
        for (int it = 0; it < 15; it++) {
            int i = tid + it * 64;
            int b = i / 15, u = i - b * 15;
            int j = u / 3, r = u - j * 3;
            dst[i] = src[b * 20 + j * 4 + r];
        }
    }
    {
        float4* dst = reinterpret_cast<float4*>(out_pf + (size_t)bBase * 36);
        const float4* src = reinterpret_cast<const float4*>(spf);
        #pragma unroll
        for (int it = 0; it < 9; it++) dst[tid + it * 64] = src[tid + it * 64];
    }
}

// ==== HMMA GEMM (64b x 192c x 96k fp16) + fused LBS, 2 CTAs/SM ====
static constexpr int LDB = 208;                   // bytes per smem row
static constexpr int SM_XH = 0;                   // X: 64*208  = 13312
static constexpr int SM_WH = 13312;               // W: 192*208 = 39936 -> 53248
static constexpr int SM_AS = 53248;               // A: 64*60*4 = 15360 -> 68608
static constexpr int SM_WJ = 68608;               // wjs: 320*4 = 1280  -> 69888
static constexpr int SM_TOTAL = 69888;            // 2 CTAs = 139776 <= 228KB
// D overlays the GEMM tiles after they are dead:
static constexpr int LDD = 196;                   // D stride in floats
static constexpr int SM_DS = 0;                   // float[64][196] = 50176 (< 53248)

__global__ __launch_bounds__(256, 2)
void skin_kernel(const float* __restrict__ lbs, float* __restrict__ out) {
    extern __shared__ char sm[];
    const uint32_t smb = smem_u32(sm);
    const int tid = threadIdx.x;
    const int wid = tid >> 5, lane = tid & 31;   // 8 warps
    const int bBase = blockIdx.y * 64;
    const int cTile = blockIdx.x;                // 192 comps = 64 vertices
    const int vBase = cTile * 64;

    // ---- stage everything up front: wjs (320 floats), X, W, A ----
    float* wjs = reinterpret_cast<float*>(sm + SM_WJ);
    #pragma unroll
    for (int it = 0; it < 2; it++) {
        int i = tid + it * 256;
        if (i < 320)
            wjs[i] = (vBase + i / 5 < NV) ? lbs[vBase * 5 + i] : 0.f;
    }
    #pragma unroll
    for (int it = 0; it < 3; it++) {
        int i = tid + it * 256;
        int r = i / KU4, u = i - r * KU4;
        *reinterpret_cast<uint4*>(sm + SM_XH + r * LDB + u * 16) =
            g_Xh4[(bBase + r) * KU4 + u];
    }
    #pragma unroll
    for (int it = 0; it < 9; it++) {
        int i = tid + it * 256;
        int r = i / KU4, u = i - r * KU4;
        *reinterpret_cast<uint4*>(sm + SM_WH + r * LDB + u * 16) =
            g_Wh4[(cTile * 192 + r) * KU4 + u];
    }
    {
        float4* As4 = reinterpret_cast<float4*>(sm + SM_AS);
        const float4* gA4 = reinterpret_cast<const float4*>(g_A);
        #pragma unroll
        for (int it = 0; it < 4; it++) {
            int i = tid + it * 256;
            if (i < 64 * 15)
                As4[i] = gA4[(size_t)bBase * 15 + i];
        }
    }
    __syncthreads();

    // ---- warp tile: 32 rows x 48 cols; warps 2x4 ----
    const int wm = wid & 1, wn = wid >> 1;
    float acc[2][6][4];
    #pragma unroll
    for (int mi = 0; mi < 2; mi++)
        #pragma unroll
        for (int ni = 0; ni < 6; ni++)
            #pragma unroll
            for (int e = 0; e < 4; e++) acc[mi][ni][e] = 0.f;

    const int a_row = wm * 32 + (lane & 7) + (lane & 8);
    const uint32_t a_off = a_row * LDB + ((lane >> 4) * 8) * 2;
    const int b_row = wn * 48 + ((lane >> 4) << 3) + (lane & 7);
    const uint32_t b_off = b_row * LDB + (((lane >> 3) & 1) * 8) * 2;
    const uint32_t xh = smb + SM_XH + a_off;
    const uint32_t wb = smb + SM_WH + b_off;

    #pragma unroll
    for (int k = 0; k < 6; k++) {
        uint32_t bfr[3][4];
        #pragma unroll
        for (int n2 = 0; n2 < 3; n2++)
            LDMATRIX_X4(bfr[n2][0], bfr[n2][1], bfr[n2][2], bfr[n2][3],
                        wb + n2 * 16 * LDB + k * 32);
        uint32_t a[2][4];
        LDMATRIX_X4(a[0][0], a[0][1], a[0][2], a[0][3], xh + k * 32);
        LDMATRIX_X4(a[1][0], a[1][1], a[1][2], a[1][3], xh + 16 * LDB + k * 32);
        #pragma unroll
        for (int mi = 0; mi < 2; mi++)
            #pragma unroll
            for (int ni = 0; ni < 6; ni++)
                MMA_FP16(acc[mi][ni], a[mi][0], a[mi][1], a[mi][2], a[mi][3],
                         bfr[ni >> 1][(ni & 1) * 2], bfr[ni >> 1][(ni & 1) * 2 + 1]);
    }
    __syncthreads();   // tiles dead; D may overlay

    // ---- stage D (64 x 196 f32) ----
    float* Ds = reinterpret_cast<float*>(sm + SM_DS);
    #pragma unroll
    for (int mi = 0; mi < 2; mi++)
        #pragma unroll
        for (int ni = 0; ni < 6; ni++) {
            int row = wm * 32 + mi * 16 + (lane >> 2);
            int col = wn * 48 + ni * 8 + (lane & 3) * 2;
            *reinterpret_cast<float2*>(Ds + row * LDD + col) =
                make_float2(acc[mi][ni][0], acc[mi][ni][1]);
            *reinterpret_cast<float2*>(Ds + (row + 8) * LDD + col) =
                make_float2(acc[mi][ni][2], acc[mi][ni][3]);
        }
    __syncthreads();

    // ---- fused LBS epilogue: results written IN PLACE into Ds ----
    const float* As = reinterpret_cast<const float*>(sm + SM_AS);
    const int lv = lane * 2;
    uint64_t w0[5], w1[5];
    #pragma unroll
    for (int j = 0; j < 5; j++) {
        float a = wjs[lv * 5 + j];
        float b = wjs[lv * 5 + 5 + j];
        w0[j] = pack2(a, a);
        w1[j] = pack2(b, b);
    }

    #pragma unroll
    for (int i = 0; i < 8; i++) {
        const int bl = wid + 8 * i;              // 0..63
        const ulonglong2* Ab = reinterpret_cast<const ulonglong2*>(As + bl * 60);
        uint64_t M0[6], M1[6];
        #pragma unroll
        for (int e = 0; e < 6; e++) { M0[e] = 0ull; M1[e] = 0ull; }
        #pragma unroll
        for (int j = 0; j < 5; j++) {
            ulonglong2 a0 = Ab[j * 3 + 0];
            ulonglong2 a1 = Ab[j * 3 + 1];
            ulonglong2 a2 = Ab[j * 3 + 2];
            fma2(M0[0], w0[j], a0.x); fma2(M0[1], w0[j], a0.y);
            fma2(M0[2], w0[j], a1.x); fma2(M0[3], w0[j], a1.y);
            fma2(M0[4], w0[j], a2.x); fma2(M0[5], w0[j], a2.y);
            fma2(M1[0], w1[j], a0.x); fma2(M1[1], w1[j], a0.y);
            fma2(M1[2], w1[j], a1.x); fma2(M1[3], w1[j], a1.y);
            fma2(M1[4], w1[j], a2.x); fma2(M1[5], w1[j], a2.y);
        }
        float* Dr = Ds + bl * LDD + lv * 3;      // thread-private 6 floats
        float2 d0 = *reinterpret_cast<const float2*>(Dr);
        float2 d1 = *reinterpret_cast<const float2*>(Dr + 2);
        float2 d2 = *reinterpret_cast<const float2*>(Dr + 4);

        float m00, m01, m02, m03, m10, m11, m12, m13, m20, m21, m22, m23;
        unpack2(M0[0], m00, m01); unpack2(M0[1], m02, m03);
        unpack2(M0[2], m10, m11); unpack2(M0[3], m12, m13);
        unpack2(M0[4], m20, m21); unpack2(M0[5], m22, m23);
        float o0 = fmaf(m00, d0.x, fmaf(m01, d0.y, fmaf(m02, d1.x, m03)));
        float o1 = fmaf(m10, d0.x, fmaf(m11, d0.y, fmaf(m12, d1.x, m13)));
        float o2 = fmaf(m20, d0.x, fmaf(m21, d0.y, fmaf(m22, d1.x, m23)));

        unpack2(M1[0], m00, m01); unpack2(M1[1], m02, m03);
        unpack2(M1[2], m10, m11); unpack2(M1[3], m12, m13);
        unpack2(M1[4], m20, m21); unpack2(M1[5], m22, m23);
        float o3 = fmaf(m00, d1.y, fmaf(m01, d2.x, fmaf(m02, d2.y, m03)));
        float o4 = fmaf(m10, d1.y, fmaf(m11, d2.x, fmaf(m12, d2.y, m13)));
        float o5 = fmaf(m20, d1.y, fmaf(m21, d2.x, fmaf(m22, d2.y, m23)));

        // in-place overwrite (reads above complete before these stores)
        *reinterpret_cast<float2*>(Dr)     = make_float2(o0, o1);
        *reinterpret_cast<float2*>(Dr + 2) = make_float2(o2, o3);
        *reinterpret_cast<float2*>(Dr + 4) = make_float2(o4, o5);
    }
    __syncthreads();

    // ---- coalesced copy Ds -> out: col = tid (192 active), strided rows ----
    if (tid < 192) {
        const float* src = Ds + tid;
        float* dst = out + (size_t)bBase * NC + (size_t)vBase * 3 + tid;
        if (vBase + 64 <= NV) {                  // full tile (78 of 79)
            #pragma unroll 8
            for (int bl = 0; bl < 64; bl++)
                dst[(size_t)bl * NC] = src[bl * LDD];
        } else if (tid < (NV - vBase) * 3) {     // tail tile, clamp columns
            #pragma unroll 8
            for (int bl = 0; bl < 64; bl++)
                dst[(size_t)bl * NC] = src[bl * LDD];
        }
    }
}

// ---------------------------------------------------------------- launch
extern "C" void kernel_launch(void* const* d_in, const int* in_sizes, int n_in,
                              void* d_out, int out_size) {
    const float* expr = (const float*)d_in[0];  // [2048,50]
    const float* pose = (const float*)d_in[1];  // [2048,15]
    const float* vt   = (const float*)d_in[2];  // [5023,3]
    const float* SD   = (const float*)d_in[3];  // [5023,3,150]
    const float* PD   = (const float*)d_in[4];  // [36,15069]
    const float* Jreg = (const float*)d_in[5];  // [5,5023]
    const float* lbs  = (const float*)d_in[6];  // [5023,5]

    float* out       = (float*)d_out;
    float* out_verts = out;                       // [B,V,3]
    float* out_pf    = out + (size_t)NB * NV * 3; // [B,36]
    float* out_A     = out_pf + (size_t)NB * 36;  // [B,5,4,4]

    const int PRE_SMEM = 256 * 104 * 2;           // 53248
    cudaFuncSetAttribute(pre_kernel,
                         cudaFuncAttributeMaxDynamicSharedMemorySize, PRE_SMEM);
    cudaFuncSetAttribute(batch_kernel,
                         cudaFuncAttributeMaxDynamicSharedMemorySize, BSM_TOTAL);
    cudaFuncSetAttribute(skin_kernel,
                         cudaFuncAttributeMaxDynamicSharedMemorySize, SM_TOTAL);

    pre_kernel<<<300, 256, PRE_SMEM>>>(vt, SD, PD, Jreg);
    jred_kernel<<<3, 256>>>();
    batch_kernel<<<NB / 64, 64, BSM_TOTAL>>>(expr, pose, out_pf, out_A);
    dim3 grid(79, 32);
    skin_kernel<<<grid, 256, SM_TOTAL>>>(lbs, out_verts);
}